// round 2
// baseline (speedup 1.0000x reference)
#include <cuda_runtime.h>
#include <math.h>

#define LEAKY 0.01f
#define TPB 256

__global__ __launch_bounds__(TPB) void mlp_fused_kernel(
    const float* __restrict__ pos, const float* __restrict__ dir,
    const float* __restrict__ pos_grid, const float* __restrict__ dir_grid,
    const float* __restrict__ W1, const float* __restrict__ b1,
    const float* __restrict__ W2, const float* __restrict__ b2,
    const float* __restrict__ W3, const float* __restrict__ b3,
    float* __restrict__ out, int N)
{
    // Stage all weights in shared memory: 384 + 64 + 4096 + 64 + 64 + 1 floats
    __shared__ float sW1[384];
    __shared__ float sb1[64];
    __shared__ float sW2[4096];
    __shared__ float sb2[64];
    __shared__ float sW3[64];
    __shared__ float sb3;

    const int t = threadIdx.x;
    for (int i = t; i < 4096; i += TPB) sW2[i] = W2[i];
    for (int i = t; i < 384;  i += TPB) sW1[i] = W1[i];
    if (t < 64) {
        sb1[t] = b1[t];
        sb2[t] = b2[t];
        sW3[t] = W3[t];
    }
    if (t == 0) sb3 = b3[0];
    __syncthreads();

    const int idx = blockIdx.x * TPB + t;
    if (idx >= N) return;

    // ---- Bilinear interpolation (matches reference formula exactly) ----
    float feat[6];
    {
        const float2 p = ((const float2*)pos)[idx];
        const float2 d = ((const float2*)dir)[idx];

        // pos lookup
        {
            float fx = p.x * 255.0f;
            float fy = p.y * 255.0f;
            int x0 = (int)fx, y0 = (int)fy;
            float xf = fx - (float)x0;
            float yf = fy - (float)y0;
            int x1 = min(x0 + 1, 255);
            int y1 = min(y0 + 1, 255);
            const float* tl = pos_grid + (y0 * 256 + x0) * 3;
            const float* tr = pos_grid + (y0 * 256 + x1) * 3;
            const float* bl = pos_grid + (y1 * 256 + x0) * 3;
            const float* br = pos_grid + (y1 * 256 + x1) * 3;
            #pragma unroll
            for (int c = 0; c < 3; c++) {
                float top = (1.0f - xf) * __ldg(tl + c) + xf * __ldg(tr + c);
                float bot = (1.0f - xf) * __ldg(bl + c) + xf * __ldg(br + c);
                feat[c] = (1.0f - yf) * top + yf * bot;
            }
        }
        // dir lookup
        {
            float fx = d.x * 255.0f;
            float fy = d.y * 255.0f;
            int x0 = (int)fx, y0 = (int)fy;
            float xf = fx - (float)x0;
            float yf = fy - (float)y0;
            int x1 = min(x0 + 1, 255);
            int y1 = min(y0 + 1, 255);
            const float* tl = dir_grid + (y0 * 256 + x0) * 3;
            const float* tr = dir_grid + (y0 * 256 + x1) * 3;
            const float* bl = dir_grid + (y1 * 256 + x0) * 3;
            const float* br = dir_grid + (y1 * 256 + x1) * 3;
            #pragma unroll
            for (int c = 0; c < 3; c++) {
                float top = (1.0f - xf) * __ldg(tl + c) + xf * __ldg(tr + c);
                float bot = (1.0f - xf) * __ldg(bl + c) + xf * __ldg(br + c);
                feat[3 + c] = (1.0f - yf) * top + yf * bot;
            }
        }
    }

    // ---- Layer 1: 6 -> 64, leaky relu; h1 kept in registers ----
    float h1[64];
    #pragma unroll
    for (int o = 0; o < 64; o++) {
        float a = sb1[o];
        #pragma unroll
        for (int i = 0; i < 6; i++)
            a = fmaf(feat[i], sW1[o * 6 + i], a);
        h1[o] = (a >= 0.0f) ? a : LEAKY * a;
    }

    // ---- Layer 2 (64 -> 64, leaky) fused with Layer 3 (64 -> 1) ----
    float acc = sb3;
    #pragma unroll 4
    for (int o = 0; o < 64; o++) {
        const float4* w4 = (const float4*)(sW2 + o * 64);
        float a0 = sb2[o];
        float a1 = 0.0f;
        #pragma unroll
        for (int i = 0; i < 16; i += 2) {
            float4 wa = w4[i];
            float4 wb = w4[i + 1];
            a0 = fmaf(h1[4*i + 0], wa.x, a0);
            a1 = fmaf(h1[4*i + 1], wa.y, a1);
            a0 = fmaf(h1[4*i + 2], wa.z, a0);
            a1 = fmaf(h1[4*i + 3], wa.w, a1);
            a0 = fmaf(h1[4*i + 4], wb.x, a0);
            a1 = fmaf(h1[4*i + 5], wb.y, a1);
            a0 = fmaf(h1[4*i + 6], wb.z, a0);
            a1 = fmaf(h1[4*i + 7], wb.w, a1);
        }
        float a = a0 + a1;
        a = (a >= 0.0f) ? a : LEAKY * a;
        acc = fmaf(a, sW3[o], acc);
    }

    // ---- Sigmoid ----
    out[idx] = 1.0f / (1.0f + __expf(-acc) * 0.0f + expf(-acc) * 1.0f);
}

extern "C" void kernel_launch(void* const* d_in, const int* in_sizes, int n_in,
                              void* d_out, int out_size)
{
    const float* pos      = (const float*)d_in[0];
    const float* dir      = (const float*)d_in[1];
    const float* pos_grid = (const float*)d_in[2];
    const float* dir_grid = (const float*)d_in[3];
    const float* W1       = (const float*)d_in[4];
    const float* b1       = (const float*)d_in[5];
    const float* W2       = (const float*)d_in[6];
    const float* b2       = (const float*)d_in[7];
    const float* W3       = (const float*)d_in[8];
    const float* b3       = (const float*)d_in[9];
    float* out            = (float*)d_out;

    const int N = in_sizes[0] / 2;  // pos is (N, 2)
    const int blocks = (N + TPB - 1) / TPB;
    mlp_fused_kernel<<<blocks, TPB>>>(pos, dir, pos_grid, dir_grid,
                                      W1, b1, W2, b2, W3, b3, out, N);
}